// round 14
// baseline (speedup 1.0000x reference)
#include <cuda_runtime.h>
#include <cuda_bf16.h>
#include <cuda_fp16.h>
#include <math.h>
#include <math_constants.h>
#include <cstdint>

#define BB 4
#define SS 2048
#define DM 1024
#define HH 16
#define DKK 64
#define MTOT (BB*SS)   // 8192

// ---------------- scratch (allocation-free) ----------------
__device__ __half g_xf[(size_t)MTOT*DM];
__device__ __half g_wf[(size_t)4*DM*DM];
__device__ __half g_vf[(size_t)BB*HH*SS*DKK];
__device__ __half g_aof[(size_t)MTOT*DM];
__device__ __nv_bfloat16 g_Qh[(size_t)BB*HH*SS*DKK], g_Ql[(size_t)BB*HH*SS*DKK];
__device__ __nv_bfloat16 g_Kh[(size_t)BB*HH*SS*DKK], g_Kl[(size_t)BB*HH*SS*DKK];
__device__ float g_rope[SS*64];   // [s][0..31]=cos, [s][32..63]=sin

#define ASCALE 0.1803368801111244f   // 1/sqrt(64)*log2(e)

// ---------------- PTX helpers ----------------
__device__ __forceinline__ uint32_t smem_to_u32(const void* p) {
    uint32_t a;
    asm("{ .reg .u64 t; cvta.to.shared.u64 t, %1; cvt.u32.u64 %0, t; }"
        : "=r"(a) : "l"(p));
    return a;
}
__device__ __forceinline__ void cp16(uint32_t dst, const void* src) {
    asm volatile("cp.async.cg.shared.global [%0], [%1], 16;"
                 :: "r"(dst), "l"(src) : "memory");
}
#define CP_COMMIT() asm volatile("cp.async.commit_group;" ::: "memory")
#define CP_WAIT1()  asm volatile("cp.async.wait_group 1;"  ::: "memory")
#define CP_WAIT0()  asm volatile("cp.async.wait_group 0;"  ::: "memory")

__device__ __forceinline__ void ldsm4(uint32_t* r, uint32_t addr) {
    asm volatile("ldmatrix.sync.aligned.m8n8.x4.shared.b16 {%0,%1,%2,%3}, [%4];"
                 : "=r"(r[0]), "=r"(r[1]), "=r"(r[2]), "=r"(r[3]) : "r"(addr));
}
__device__ __forceinline__ void ldsm4t(uint32_t* r, uint32_t addr) {
    asm volatile("ldmatrix.sync.aligned.m8n8.x4.trans.shared.b16 {%0,%1,%2,%3}, [%4];"
                 : "=r"(r[0]), "=r"(r[1]), "=r"(r[2]), "=r"(r[3]) : "r"(addr));
}
// bf16 mma (score path)
__device__ __forceinline__ void mma16816(float* d, const uint32_t* a,
                                         uint32_t b0, uint32_t b1) {
    asm volatile("mma.sync.aligned.m16n8k16.row.col.f32.bf16.bf16.f32 "
                 "{%0,%1,%2,%3}, {%4,%5,%6,%7}, {%8,%9}, {%0,%1,%2,%3};"
                 : "+f"(d[0]), "+f"(d[1]), "+f"(d[2]), "+f"(d[3])
                 : "r"(a[0]), "r"(a[1]), "r"(a[2]), "r"(a[3]), "r"(b0), "r"(b1));
}
// fp16 mma (projections / PV / Wo)
__device__ __forceinline__ void mma16816h(float* d, const uint32_t* a,
                                          uint32_t b0, uint32_t b1) {
    asm volatile("mma.sync.aligned.m16n8k16.row.col.f32.f16.f16.f32 "
                 "{%0,%1,%2,%3}, {%4,%5,%6,%7}, {%8,%9}, {%0,%1,%2,%3};"
                 : "+f"(d[0]), "+f"(d[1]), "+f"(d[2]), "+f"(d[3])
                 : "r"(a[0]), "r"(a[1]), "r"(a[2]), "r"(a[3]), "r"(b0), "r"(b1));
}
__device__ __forceinline__ float ex2(float x) {
    float y;
    asm("ex2.approx.f32 %0, %1;" : "=f"(y) : "f"(x));
    return y;
}
__device__ __forceinline__ uint32_t packbf(float lo, float hi) {
    uint32_t r;
    asm("cvt.rn.bf16x2.f32 %0, %1, %2;" : "=r"(r) : "f"(hi), "f"(lo));
    return r;
}
__device__ __forceinline__ uint32_t packhf(float lo, float hi) {
    uint32_t r;
    asm("cvt.rn.f16x2.f32 %0, %1, %2;" : "=r"(r) : "f"(hi), "f"(lo));
    return r;
}
__device__ __forceinline__ void split2(float d0, float d1, uint32_t& uh, uint32_t& ul) {
    uh = packbf(d0, d1);
    float h0 = __uint_as_float(uh << 16);
    float h1 = __uint_as_float(uh & 0xffff0000u);
    ul = packbf(d0 - h0, d1 - h1);
}

// ---------------------------------------------------------------------------
// fp32 -> fp16 conversions
// ---------------------------------------------------------------------------
__global__ void cvt_kernel(const float* __restrict__ src, __half* __restrict__ dst, int n4)
{
    int i = blockIdx.x * blockDim.x + threadIdx.x;
    if (i >= n4) return;
    float4 v = ((const float4*)src)[i];
    ((uint2*)dst)[i] = make_uint2(packhf(v.x, v.y), packhf(v.z, v.w));
}

__global__ void cvt_w_kernel(const float* __restrict__ w0, const float* __restrict__ w1,
                             const float* __restrict__ w2, const float* __restrict__ w3,
                             __half* __restrict__ dst)
{
    const int wsel = blockIdx.y;
    const float* src = (wsel == 0) ? w0 : (wsel == 1) ? w1 : (wsel == 2) ? w2 : w3;
    size_t off = (size_t)wsel * (DM * DM / 4);
    int i = blockIdx.x * blockDim.x + threadIdx.x;
    float4 v = ((const float4*)src)[i];
    ((uint2*)dst)[off + i] = make_uint2(packhf(v.x, v.y), packhf(v.z, v.w));
}

__global__ void rope_init_kernel(const int* __restrict__ tokpos, float* __restrict__ rope)
{
    int idx = blockIdx.x * blockDim.x + threadIdx.x;
    int s = idx >> 5, p = idx & 31;
    float fr = (float)exp2(-(double)p * (13.287712379549449 / 32.0));
    float ang = (float)tokpos[s] * fr;
    float sn, cs;
    sincosf(ang, &sn, &cs);
    rope[s * 64 + p] = cs;
    rope[s * 64 + 32 + p] = sn;
}

// ---------------------------------------------------------------------------
// fp16 single-term GEMM, 3-stage cp.async pipeline, 2 CTAs/SM.
// Loop: wait1 (chunk kc ready, kc+1 in flight) -> sync -> issue kc+2 -> compute.
// ---------------------------------------------------------------------------
#define GP      40
#define TILE_B  (128*GP*2)         // 10240 bytes (128 rows x 80B pitch)
#define STAGE_B (2*TILE_B)         // 20480 (A | B)
#define GSMEM   (3*STAGE_B)        // 61440

__device__ __forceinline__ void issue_stage(uint32_t sdst,
    const __half* __restrict__ A, const __half* __restrict__ B,
    int m0, int n0, int kc, int tid)
{
    const int colb = kc * 64;
#pragma unroll
    for (int it = 0; it < 2; it++) {
        int idx = tid + it * 256;
        int row = idx >> 2;
        int ch  = (idx & 3) * 16;
        uint32_t soff = row * 80 + ch;
        cp16(sdst + soff,          (const char*)(A + (size_t)(m0 + row) * DM) + colb + ch);
        cp16(sdst + TILE_B + soff, (const char*)(B + (size_t)(n0 + row) * DM) + colb + ch);
    }
}

__global__ __launch_bounds__(256, 2)
void gemm_h(const __half* __restrict__ A, const __half* __restrict__ WBase,
            float* __restrict__ out,
            __nv_bfloat16* __restrict__ qh, __nv_bfloat16* __restrict__ ql,
            __nv_bfloat16* __restrict__ kh, __nv_bfloat16* __restrict__ kl,
            __half* __restrict__ vf,
            const float* __restrict__ rope, int wo)
{
    extern __shared__ char smc[];
    const uint32_t sbase = smem_to_u32(smc);

    const int tid  = threadIdx.x;
    const int wid  = tid >> 5;
    const int lane = tid & 31;
    const int m0 = blockIdx.x * 128;
    const int by = blockIdx.y;
    const int wsel = wo ? 3 : (by >> 3);
    const int n0 = wo ? by * 128 : (by & 7) * 128;
    const __half* B = WBase + (size_t)wsel * DM * DM;

    const int wm = (wid & 3) * 32;
    const int wn = (wid >> 2) * 64;

    float acc[2][8][4];
#pragma unroll
    for (int i = 0; i < 2; i++)
#pragma unroll
        for (int j = 0; j < 8; j++)
#pragma unroll
            for (int q = 0; q < 4; q++) acc[i][j][q] = 0.f;

    const uint32_t lrow = (lane & 7) + ((lane >> 3) & 1) * 8;
    const uint32_t kbl  = ((lane >> 4) & 1) * 16;

    issue_stage(sbase + 0 * STAGE_B, A, B, m0, n0, 0, tid);
    CP_COMMIT();
    issue_stage(sbase + 1 * STAGE_B, A, B, m0, n0, 1, tid);
    CP_COMMIT();

    const int NKC = DM / 32;   // 32
    for (int kc = 0; kc < NKC; kc++) {
        if (kc + 1 < NKC) CP_WAIT1(); else CP_WAIT0();
        __syncthreads();
        if (kc + 2 < NKC) {
            issue_stage(sbase + ((kc + 2) % 3) * STAGE_B, A, B, m0, n0, kc + 2, tid);
            CP_COMMIT();
        }

        const uint32_t sb = sbase + (kc % 3) * STAGE_B;
#pragma unroll
        for (int ks = 0; ks < 2; ks++) {
            const uint32_t kb = ks * 32 + kbl;
            uint32_t a0[4], a1[4];
            const uint32_t aadr = sb + (wm + lrow) * 80 + kb;
            ldsm4(a0, aadr);
            ldsm4(a1, aadr + 16 * 80);
#pragma unroll
            for (int nb = 0; nb < 4; nb++) {
                uint32_t bf[4];
                const uint32_t badr = sb + TILE_B + (wn + nb * 16 + lrow) * 80 + kb;
                ldsm4(bf, badr);
#pragma unroll
                for (int sel = 0; sel < 2; sel++) {
                    const int nj = nb * 2 + sel;
                    mma16816h(acc[0][nj], a0, bf[sel], bf[sel + 2]);
                    mma16816h(acc[1][nj], a1, bf[sel], bf[sel + 2]);
                }
            }
        }
    }

    // ---- epilogue ----
    const int g = lane >> 2;
    const int t2 = (lane & 3) * 2;
#pragma unroll
    for (int mi = 0; mi < 2; mi++) {
#pragma unroll
        for (int half = 0; half < 2; half++) {
            const int r = m0 + wm + mi * 16 + half * 8 + g;
            const int b = r >> 11;
            const int s = r & 2047;
#pragma unroll
            for (int nj = 0; nj < 8; nj++) {
                const int e = n0 + wn + nj * 8 + t2;
                float d0 = acc[mi][nj][half * 2 + 0];
                float d1 = acc[mi][nj][half * 2 + 1];
                if (wsel == 3) {
                    *(float2*)&out[(size_t)r * DM + e] = make_float2(d0, d1);
                } else {
                    const int h  = e >> 6;
                    const int dk = e & 63;
                    size_t idx = ((size_t)(b * HH + h) * SS + s) * DKK + dk;
                    if (wsel == 2) {
                        *(uint32_t*)&vf[idx] = packhf(d0, d1);
                    } else {
                        const int p = dk >> 1;
                        float cs = __ldg(&rope[s * 64 + p]);
                        float sn = __ldg(&rope[s * 64 + 32 + p]);
                        float r0 = d0 * cs - d1 * sn;
                        float r1 = d0 * sn + d1 * cs;
                        if (wsel == 0) { r0 *= ASCALE; r1 *= ASCALE; }
                        uint32_t uh, ul;
                        split2(r0, r1, uh, ul);
                        __nv_bfloat16* oh = (wsel == 0) ? qh : kh;
                        __nv_bfloat16* ol = (wsel == 0) ? ql : kl;
                        *(uint32_t*)&oh[idx] = uh;
                        *(uint32_t*)&ol[idx] = ul;
                    }
                }
            }
        }
    }
}

// ---------------------------------------------------------------------------
// Flash attention: S-phase bf16x3, PV-phase fp16 single. 2-stage KV, 2 CTAs/SM.
// Unchanged from round 13 (validated, 507 µs config).
// ---------------------------------------------------------------------------
#define AP      144
#define QT_B    (128*AP)      // 18432
#define KT_B    (64*AP)       // 9216
#define ASTG_B  (3*KT_B)      // 27648
#define ASMEM   (2*QT_B + 2*ASTG_B)   // 92160

__device__ __forceinline__ void issue_kv(uint32_t dst,
    const __nv_bfloat16* __restrict__ Kh, const __nv_bfloat16* __restrict__ Kl,
    const __half* __restrict__ Vf,
    size_t base, int kb, int tid)
{
#pragma unroll
    for (int it = 0; it < 6; it++) {
        int f   = tid + it * 256;
        int ten = f >> 9;
        int row = (f >> 3) & 63;
        int ch  = f & 7;
        const void* sp;
        if (ten == 0)      sp = Kh + base + (size_t)(kb * 64 + row) * DKK + ch * 8;
        else if (ten == 1) sp = Kl + base + (size_t)(kb * 64 + row) * DKK + ch * 8;
        else               sp = Vf + base + (size_t)(kb * 64 + row) * DKK + ch * 8;
        cp16(dst + ten * KT_B + row * AP + ch * 16, sp);
    }
}

__global__ __launch_bounds__(256, 2)
void attn_mma(const __nv_bfloat16* __restrict__ Qh, const __nv_bfloat16* __restrict__ Ql,
              const __nv_bfloat16* __restrict__ Kh, const __nv_bfloat16* __restrict__ Kl,
              const __half* __restrict__ Vf,
              __half* __restrict__ AOf)
{
    extern __shared__ char smc[];
    const uint32_t sb = smem_to_u32(smc);
    const uint32_t sQ  = sb;
    const uint32_t sKV = sb + 2 * QT_B;

    const int tid  = threadIdx.x;
    const int wid  = tid >> 5;
    const int lane = tid & 31;
    const int g = lane >> 2;
    const int t = lane & 3;

    const int qb = 15 - (blockIdx.x >> 6);
    const int bh = blockIdx.x & 63;
    const size_t base = (size_t)bh * SS * DKK;
    const int nkb = 2 * qb + 2;

    const float NINF = __int_as_float(0xff800000);

#pragma unroll
    for (int it = 0; it < 8; it++) {
        int f   = tid + it * 256;
        int ten = f >> 10;
        int row = (f >> 3) & 127;
        int ch  = f & 7;
        const __nv_bfloat16* sp = (ten ? Ql : Qh)
            + base + (size_t)(qb * 128 + row) * DKK + ch * 8;
        cp16(sQ + ten * QT_B + row * AP + ch * 16, sp);
    }
    issue_kv(sKV, Kh, Kl, Vf, base, 0, tid);
    CP_COMMIT();
    issue_kv(sKV + ASTG_B, Kh, Kl, Vf, base, 1, tid);
    CP_COMMIT();

    CP_WAIT1();
    __syncthreads();

    const uint32_t lrow = (lane & 7) + ((lane >> 3) & 1) * 8;
    const uint32_t kb16 = ((lane >> 4) & 1) * 16;
    uint32_t qfh[4][4], qfl[4][4];
#pragma unroll
    for (int ks = 0; ks < 4; ks++) {
        uint32_t a = sQ + (wid * 16 + lrow) * AP + ks * 32 + kb16;
        ldsm4(qfh[ks], a);
        ldsm4(qfl[ks], a + QT_B);
    }

    float oacc[8][4];
#pragma unroll
    for (int nj = 0; nj < 8; nj++)
#pragma unroll
        for (int q = 0; q < 4; q++) oacc[nj][q] = 0.f;
    float m0 = NINF, m1 = NINF, l0 = 0.f, l1 = 0.f;

    const int r0 = qb * 128 + wid * 16 + g;
    const int r1 = r0 + 8;

    const uint32_t vrow = (lane & 7) + ((lane >> 4) & 1) * 8;
    const uint32_t vb16 = ((lane >> 3) & 1) * 16;

    for (int kb = 0; kb < nkb; kb++) {
        if (kb + 1 < nkb) CP_WAIT1(); else CP_WAIT0();
        __syncthreads();

        const uint32_t sK = sKV + (kb & 1) * ASTG_B;
        const uint32_t sV = sK + 2 * KT_B;

        float sf[8][4];
#pragma unroll
        for (int nj = 0; nj < 8; nj++)
#pragma unroll
            for (int q = 0; q < 4; q++) sf[nj][q] = 0.f;

#pragma unroll
        for (int ks = 0; ks < 4; ks++) {
#pragma unroll
            for (int ntp = 0; ntp < 2; ntp++) {
                uint32_t kfh[2][4], kfl[2][4];
#pragma unroll
                for (int nt2 = 0; nt2 < 2; nt2++) {
                    uint32_t ba = sK + ((ntp * 2 + nt2) * 16 + lrow) * AP + ks * 32 + kb16;
                    ldsm4(kfh[nt2], ba);
                    ldsm4(kfl[nt2], ba + KT_B);
                }
#pragma unroll
                for (int term = 0; term < 3; term++) {
                    const uint32_t* a = (term == 2) ? qfl[ks] : qfh[ks];
#pragma unroll
                    for (int nt2 = 0; nt2 < 2; nt2++) {
#pragma unroll
                        for (int sel = 0; sel < 2; sel++) {
                            const int nj = (ntp * 2 + nt2) * 2 + sel;
                            const uint32_t b0 = (term == 1) ? kfl[nt2][sel]     : kfh[nt2][sel];
                            const uint32_t b1 = (term == 1) ? kfl[nt2][sel + 2] : kfh[nt2][sel + 2];
                            mma16816(sf[nj], a, b0, b1);
                        }
                    }
                }
            }
        }

        if (kb >= 2 * qb) {
#pragma unroll
            for (int nj = 0; nj < 8; nj++) {
                int c0 = kb * 64 + nj * 8 + 2 * t;
                if (c0 > r0)     sf[nj][0] = NINF;
                if (c0 + 1 > r0) sf[nj][1] = NINF;
                if (c0 > r1)     sf[nj][2] = NINF;
                if (c0 + 1 > r1) sf[nj][3] = NINF;
            }
        }

        float mx0 = sf[0][0], mx1 = sf[0][2];
#pragma unroll
        for (int nj = 0; nj < 8; nj++) {
            mx0 = fmaxf(mx0, fmaxf(sf[nj][0], sf[nj][1]));
            mx1 = fmaxf(mx1, fmaxf(sf[nj][2], sf[nj][3]));
        }
        mx0 = fmaxf(mx0, __shfl_xor_sync(0xffffffffu, mx0, 1));
        mx0 = fmaxf(mx0, __shfl_xor_sync(0xffffffffu, mx0, 2));
        mx1 = fmaxf(mx1, __shfl_xor_sync(0xffffffffu, mx1, 1));
        mx1 = fmaxf(mx1, __shfl_xor_sync(0xffffffffu, mx1, 2));
        float mn0 = fmaxf(m0, mx0), mn1 = fmaxf(m1, mx1);
        float al0 = ex2(m0 - mn0), al1 = ex2(m1 - mn1);
        m0 = mn0; m1 = mn1;

        float s0 = 0.f, s1 = 0.f;
#pragma unroll
        for (int nj = 0; nj < 8; nj++) {
            sf[nj][0] = ex2(sf[nj][0] - m0);
            sf[nj][1] = ex2(sf[nj][1] - m0);
            sf[nj][2] = ex2(sf[nj][2] - m1);
            sf[nj][3] = ex2(sf[nj][3] - m1);
            s0 += sf[nj][0] + sf[nj][1];
            s1 += sf[nj][2] + sf[nj][3];
        }
        s0 += __shfl_xor_sync(0xffffffffu, s0, 1);
        s0 += __shfl_xor_sync(0xffffffffu, s0, 2);
        s1 += __shfl_xor_sync(0xffffffffu, s1, 1);
        s1 += __shfl_xor_sync(0xffffffffu, s1, 2);
        l0 = l0 * al0 + s0;
        l1 = l1 * al1 + s1;

#pragma unroll
        for (int nj = 0; nj < 8; nj++) {
            oacc[nj][0] *= al0; oacc[nj][1] *= al0;
            oacc[nj][2] *= al1; oacc[nj][3] *= al1;
        }

#pragma unroll
        for (int ks = 0; ks < 4; ks++) {
            uint32_t pa[4];
            pa[0] = packhf(sf[2 * ks][0],     sf[2 * ks][1]);
            pa[1] = packhf(sf[2 * ks][2],     sf[2 * ks][3]);
            pa[2] = packhf(sf[2 * ks + 1][0], sf[2 * ks + 1][1]);
            pa[3] = packhf(sf[2 * ks + 1][2], sf[2 * ks + 1][3]);
#pragma unroll
            for (int ntp = 0; ntp < 2; ntp++) {
                uint32_t vfr[2][4];
#pragma unroll
                for (int nt2 = 0; nt2 < 2; nt2++) {
                    uint32_t va = sV + (ks * 16 + vrow) * AP + (ntp * 2 + nt2) * 32 + vb16;
                    ldsm4t(vfr[nt2], va);
                }
#pragma unroll
                for (int nt2 = 0; nt2 < 2; nt2++) {
#pragma unroll
                    for (int sel = 0; sel < 2; sel++) {
                        const int nj = (ntp * 2 + nt2) * 2 + sel;
                        mma16816h(oacc[nj], pa, vfr[nt2][sel], vfr[nt2][sel + 2]);
                    }
                }
            }
        }
        __syncthreads();

        if (kb + 2 < nkb) {
            issue_kv(sKV + (kb & 1) * ASTG_B, Kh, Kl, Vf, base, kb + 2, tid);
            CP_COMMIT();
        }
    }

    // ---- epilogue ----
    const float inv0 = 1.0f / l0;
    const float inv1 = 1.0f / l1;
    const int b = bh >> 4, h = bh & 15;
    const size_t row0 = (size_t)(b * SS + r0) * DM;
    const size_t row1 = (size_t)(b * SS + r1) * DM;
#pragma unroll
    for (int nj = 0; nj < 8; nj++) {
        const int e = h * 64 + nj * 8 + 2 * t;
        *(uint32_t*)&AOf[row0 + e] = packhf(oacc[nj][0] * inv0, oacc[nj][1] * inv0);
        *(uint32_t*)&AOf[row1 + e] = packhf(oacc[nj][2] * inv1, oacc[nj][3] * inv1);
    }
}

// ---------------------------------------------------------------------------
extern "C" void kernel_launch(void* const* d_in, const int* in_sizes, int n_in,
                              void* d_out, int out_size)
{
    const float* x  = (const float*)d_in[0];
    const float* Wq = (const float*)d_in[1];
    const float* Wk = (const float*)d_in[2];
    const float* Wv = (const float*)d_in[3];
    const float* Wo = (const float*)d_in[4];
    const int*   tp = (const int*)  d_in[5];
    float* out = (float*)d_out;

    float* gRope;
    __half *xf, *wf, *vf, *aof;
    __nv_bfloat16 *qh, *ql, *kh, *kl;
    cudaGetSymbolAddress((void**)&gRope, g_rope);
    cudaGetSymbolAddress((void**)&xf,  g_xf);
    cudaGetSymbolAddress((void**)&wf,  g_wf);
    cudaGetSymbolAddress((void**)&vf,  g_vf);
    cudaGetSymbolAddress((void**)&aof, g_aof);
    cudaGetSymbolAddress((void**)&qh,  g_Qh);
    cudaGetSymbolAddress((void**)&ql,  g_Ql);
    cudaGetSymbolAddress((void**)&kh,  g_Kh);
    cudaGetSymbolAddress((void**)&kl,  g_Kl);

    cudaFuncSetAttribute(gemm_h,   cudaFuncAttributeMaxDynamicSharedMemorySize, GSMEM);
    cudaFuncSetAttribute(attn_mma, cudaFuncAttributeMaxDynamicSharedMemorySize, ASMEM);

    const int nx4 = MTOT * DM / 4;
    const int nw4 = DM * DM / 4;
    cvt_kernel<<<nx4 / 256, 256>>>(x, xf, nx4);
    dim3 wgrid(nw4 / 256, 4);
    cvt_w_kernel<<<wgrid, 256>>>(Wq, Wk, Wv, Wo, wf);
    rope_init_kernel<<<SS * 32 / 256, 256>>>(tp, gRope);

    dim3 qkvgrid(MTOT / 128, 24);   // (64, 24)
    gemm_h<<<qkvgrid, 256, GSMEM>>>(xf, wf, nullptr,
                                    qh, ql, kh, kl, vf, gRope, 0);

    attn_mma<<<1024, 256, ASMEM>>>(qh, ql, kh, kl, vf, aof);

    dim3 wogrid(MTOT / 128, 8);     // (64, 8)
    gemm_h<<<wogrid, 256, GSMEM>>>(aof, wf, out,
                                   qh, ql, kh, kl, vf, gRope, 1);
}

// round 15
// speedup vs baseline: 1.1400x; 1.1400x over previous
#include <cuda_runtime.h>
#include <cuda_bf16.h>
#include <cuda_fp16.h>
#include <math.h>
#include <math_constants.h>
#include <cstdint>

#define BB 4
#define SS 2048
#define DM 1024
#define HH 16
#define DKK 64
#define MTOT (BB*SS)   // 8192

// ---------------- scratch (allocation-free) ----------------
__device__ __half g_xf[(size_t)MTOT*DM];
__device__ __half g_wf[(size_t)4*DM*DM];
__device__ __half g_vf[(size_t)BB*HH*SS*DKK];
__device__ __half g_aof[(size_t)MTOT*DM];
__device__ __half g_Qh[(size_t)BB*HH*SS*DKK], g_Ql[(size_t)BB*HH*SS*DKK];
__device__ __half g_Kf[(size_t)BB*HH*SS*DKK];
__device__ float g_rope[SS*64];   // [s][0..31]=cos, [s][32..63]=sin

#define ASCALE 0.1803368801111244f   // 1/sqrt(64)*log2(e)

// ---------------- PTX helpers ----------------
__device__ __forceinline__ uint32_t smem_to_u32(const void* p) {
    uint32_t a;
    asm("{ .reg .u64 t; cvta.to.shared.u64 t, %1; cvt.u32.u64 %0, t; }"
        : "=r"(a) : "l"(p));
    return a;
}
__device__ __forceinline__ void cp16(uint32_t dst, const void* src) {
    asm volatile("cp.async.cg.shared.global [%0], [%1], 16;"
                 :: "r"(dst), "l"(src) : "memory");
}
#define CP_COMMIT() asm volatile("cp.async.commit_group;" ::: "memory")
#define CP_WAIT1()  asm volatile("cp.async.wait_group 1;"  ::: "memory")
#define CP_WAIT0()  asm volatile("cp.async.wait_group 0;"  ::: "memory")

__device__ __forceinline__ void ldsm4(uint32_t* r, uint32_t addr) {
    asm volatile("ldmatrix.sync.aligned.m8n8.x4.shared.b16 {%0,%1,%2,%3}, [%4];"
                 : "=r"(r[0]), "=r"(r[1]), "=r"(r[2]), "=r"(r[3]) : "r"(addr));
}
__device__ __forceinline__ void ldsm4t(uint32_t* r, uint32_t addr) {
    asm volatile("ldmatrix.sync.aligned.m8n8.x4.trans.shared.b16 {%0,%1,%2,%3}, [%4];"
                 : "=r"(r[0]), "=r"(r[1]), "=r"(r[2]), "=r"(r[3]) : "r"(addr));
}
// fp16 mma (all matmuls)
__device__ __forceinline__ void mma16816h(float* d, const uint32_t* a,
                                          uint32_t b0, uint32_t b1) {
    asm volatile("mma.sync.aligned.m16n8k16.row.col.f32.f16.f16.f32 "
                 "{%0,%1,%2,%3}, {%4,%5,%6,%7}, {%8,%9}, {%0,%1,%2,%3};"
                 : "+f"(d[0]), "+f"(d[1]), "+f"(d[2]), "+f"(d[3])
                 : "r"(a[0]), "r"(a[1]), "r"(a[2]), "r"(a[3]), "r"(b0), "r"(b1));
}
__device__ __forceinline__ float ex2(float x) {
    float y;
    asm("ex2.approx.f32 %0, %1;" : "=f"(y) : "f"(x));
    return y;
}
__device__ __forceinline__ uint32_t packhf(float lo, float hi) {
    uint32_t r;
    asm("cvt.rn.f16x2.f32 %0, %1, %2;" : "=r"(r) : "f"(hi), "f"(lo));
    return r;
}
// fp16 two-digit split: x = h + l with h=fp16(x), l=fp16(x-h)
__device__ __forceinline__ void split2h(float d0, float d1, uint32_t& uh, uint32_t& ul) {
    uh = packhf(d0, d1);
    __half2 hh = *(__half2*)&uh;
    float h0 = __half2float(__low2half(hh));
    float h1 = __half2float(__high2half(hh));
    ul = packhf(d0 - h0, d1 - h1);
}

// ---------------------------------------------------------------------------
// fp32 -> fp16 conversions
// ---------------------------------------------------------------------------
__global__ void cvt_kernel(const float* __restrict__ src, __half* __restrict__ dst, int n4)
{
    int i = blockIdx.x * blockDim.x + threadIdx.x;
    if (i >= n4) return;
    float4 v = ((const float4*)src)[i];
    ((uint2*)dst)[i] = make_uint2(packhf(v.x, v.y), packhf(v.z, v.w));
}

__global__ void cvt_w_kernel(const float* __restrict__ w0, const float* __restrict__ w1,
                             const float* __restrict__ w2, const float* __restrict__ w3,
                             __half* __restrict__ dst)
{
    const int wsel = blockIdx.y;
    const float* src = (wsel == 0) ? w0 : (wsel == 1) ? w1 : (wsel == 2) ? w2 : w3;
    size_t off = (size_t)wsel * (DM * DM / 4);
    int i = blockIdx.x * blockDim.x + threadIdx.x;
    float4 v = ((const float4*)src)[i];
    ((uint2*)dst)[off + i] = make_uint2(packhf(v.x, v.y), packhf(v.z, v.w));
}

__global__ void rope_init_kernel(const int* __restrict__ tokpos, float* __restrict__ rope)
{
    int idx = blockIdx.x * blockDim.x + threadIdx.x;
    int s = idx >> 5, p = idx & 31;
    float fr = (float)exp2(-(double)p * (13.287712379549449 / 32.0));
    float ang = (float)tokpos[s] * fr;
    float sn, cs;
    sincosf(ang, &sn, &cs);
    rope[s * 64 + p] = cs;
    rope[s * 64 + 32 + p] = sn;
}

// ---------------------------------------------------------------------------
// fp16 single-term GEMM, 2-stage cp.async (round-13 validated structure).
// wsel 0: RoPE*ASCALE -> Q fp16 hi/lo; 1: RoPE -> K fp16; 2: -> V fp16;
// 3: fp32 -> out.
// ---------------------------------------------------------------------------
#define GP      40
#define TILE_B  (128*GP*2)         // 10240 bytes
#define STAGE_B (2*TILE_B)         // 20480 (A | B)
#define GSMEM   (2*STAGE_B)        // 40960

__device__ __forceinline__ void issue_stage(uint32_t sdst,
    const __half* __restrict__ A, const __half* __restrict__ B,
    int m0, int n0, int kc, int tid)
{
    const int colb = kc * 64;
#pragma unroll
    for (int it = 0; it < 2; it++) {
        int idx = tid + it * 256;
        int row = idx >> 2;
        int ch  = (idx & 3) * 16;
        uint32_t soff = row * 80 + ch;
        cp16(sdst + soff,          (const char*)(A + (size_t)(m0 + row) * DM) + colb + ch);
        cp16(sdst + TILE_B + soff, (const char*)(B + (size_t)(n0 + row) * DM) + colb + ch);
    }
}

__global__ __launch_bounds__(256, 2)
void gemm_h(const __half* __restrict__ A, const __half* __restrict__ WBase,
            float* __restrict__ out,
            __half* __restrict__ qh, __half* __restrict__ ql,
            __half* __restrict__ kf, __half* __restrict__ vf,
            const float* __restrict__ rope, int wo)
{
    extern __shared__ char smc[];
    const uint32_t sbase = smem_to_u32(smc);

    const int tid  = threadIdx.x;
    const int wid  = tid >> 5;
    const int lane = tid & 31;
    const int m0 = blockIdx.x * 128;
    const int by = blockIdx.y;
    const int wsel = wo ? 3 : (by >> 3);
    const int n0 = wo ? by * 128 : (by & 7) * 128;
    const __half* B = WBase + (size_t)wsel * DM * DM;

    const int wm = (wid & 3) * 32;
    const int wn = (wid >> 2) * 64;

    float acc[2][8][4];
#pragma unroll
    for (int i = 0; i < 2; i++)
#pragma unroll
        for (int j = 0; j < 8; j++)
#pragma unroll
            for (int q = 0; q < 4; q++) acc[i][j][q] = 0.f;

    const uint32_t lrow = (lane & 7) + ((lane >> 3) & 1) * 8;
    const uint32_t kbl  = ((lane >> 4) & 1) * 16;

    issue_stage(sbase, A, B, m0, n0, 0, tid);
    CP_COMMIT();

    const int NKC = DM / 32;   // 32
    for (int kc = 0; kc < NKC; kc++) {
        CP_WAIT0();
        __syncthreads();
        if (kc + 1 < NKC) {
            issue_stage(sbase + ((kc + 1) & 1) * STAGE_B, A, B, m0, n0, kc + 1, tid);
            CP_COMMIT();
        }

        const uint32_t sb = sbase + (kc & 1) * STAGE_B;
#pragma unroll
        for (int ks = 0; ks < 2; ks++) {
            const uint32_t kb = ks * 32 + kbl;
            uint32_t a0[4], a1[4];
            const uint32_t aadr = sb + (wm + lrow) * 80 + kb;
            ldsm4(a0, aadr);
            ldsm4(a1, aadr + 16 * 80);
#pragma unroll
            for (int nb = 0; nb < 4; nb++) {
                uint32_t bf[4];
                const uint32_t badr = sb + TILE_B + (wn + nb * 16 + lrow) * 80 + kb;
                ldsm4(bf, badr);
#pragma unroll
                for (int sel = 0; sel < 2; sel++) {
                    const int nj = nb * 2 + sel;
                    mma16816h(acc[0][nj], a0, bf[sel], bf[sel + 2]);
                    mma16816h(acc[1][nj], a1, bf[sel], bf[sel + 2]);
                }
            }
        }
    }

    // ---- epilogue ----
    const int g = lane >> 2;
    const int t2 = (lane & 3) * 2;
#pragma unroll
    for (int mi = 0; mi < 2; mi++) {
#pragma unroll
        for (int half = 0; half < 2; half++) {
            const int r = m0 + wm + mi * 16 + half * 8 + g;
            const int b = r >> 11;
            const int s = r & 2047;
#pragma unroll
            for (int nj = 0; nj < 8; nj++) {
                const int e = n0 + wn + nj * 8 + t2;
                float d0 = acc[mi][nj][half * 2 + 0];
                float d1 = acc[mi][nj][half * 2 + 1];
                if (wsel == 3) {
                    *(float2*)&out[(size_t)r * DM + e] = make_float2(d0, d1);
                } else {
                    const int h  = e >> 6;
                    const int dk = e & 63;
                    size_t idx = ((size_t)(b * HH + h) * SS + s) * DKK + dk;
                    if (wsel == 2) {
                        *(uint32_t*)&vf[idx] = packhf(d0, d1);
                    } else {
                        const int p = dk >> 1;
                        float cs = __ldg(&rope[s * 64 + p]);
                        float sn = __ldg(&rope[s * 64 + 32 + p]);
                        float r0 = d0 * cs - d1 * sn;
                        float r1 = d0 * sn + d1 * cs;
                        if (wsel == 0) {
                            r0 *= ASCALE; r1 *= ASCALE;
                            uint32_t uh, ul;
                            split2h(r0, r1, uh, ul);
                            *(uint32_t*)&qh[idx] = uh;
                            *(uint32_t*)&ql[idx] = ul;
                        } else {
                            *(uint32_t*)&kf[idx] = packhf(r0, r1);
                        }
                    }
                }
            }
        }
    }
}

// ---------------------------------------------------------------------------
// Flash attention: S = Qh*K + Ql*K (fp16 2-term), PV fp16 single.
// 2-stage KV (Kf | Vf per stage), 2 CTAs/SM.
// ---------------------------------------------------------------------------
#define AP      144
#define QT_B    (128*AP)      // 18432
#define KT_B    (64*AP)       // 9216
#define ASTG_B  (2*KT_B)      // 18432
#define ASMEM   (2*QT_B + 2*ASTG_B)   // 73728

__device__ __forceinline__ void issue_kv(uint32_t dst,
    const __half* __restrict__ Kf, const __half* __restrict__ Vf,
    size_t base, int kb, int tid)
{
#pragma unroll
    for (int it = 0; it < 4; it++) {
        int f   = tid + it * 256;       // 0..1023
        int ten = f >> 9;               // 0,1
        int row = (f >> 3) & 63;
        int ch  = f & 7;
        const __half* sp = (ten ? Vf : Kf)
            + base + (size_t)(kb * 64 + row) * DKK + ch * 8;
        cp16(dst + ten * KT_B + row * AP + ch * 16, sp);
    }
}

__global__ __launch_bounds__(256, 2)
void attn_mma(const __half* __restrict__ Qh, const __half* __restrict__ Ql,
              const __half* __restrict__ Kf, const __half* __restrict__ Vf,
              __half* __restrict__ AOf)
{
    extern __shared__ char smc[];
    const uint32_t sb = smem_to_u32(smc);
    const uint32_t sQ  = sb;
    const uint32_t sKV = sb + 2 * QT_B;

    const int tid  = threadIdx.x;
    const int wid  = tid >> 5;
    const int lane = tid & 31;
    const int g = lane >> 2;
    const int t = lane & 3;

    const int qb = 15 - (blockIdx.x >> 6);    // heavy q-blocks first
    const int bh = blockIdx.x & 63;
    const size_t base = (size_t)bh * SS * DKK;
    const int nkb = 2 * qb + 2;

    const float NINF = __int_as_float(0xff800000);

#pragma unroll
    for (int it = 0; it < 8; it++) {
        int f   = tid + it * 256;
        int ten = f >> 10;
        int row = (f >> 3) & 127;
        int ch  = f & 7;
        const __half* sp = (ten ? Ql : Qh)
            + base + (size_t)(qb * 128 + row) * DKK + ch * 8;
        cp16(sQ + ten * QT_B + row * AP + ch * 16, sp);
    }
    issue_kv(sKV, Kf, Vf, base, 0, tid);
    CP_COMMIT();
    issue_kv(sKV + ASTG_B, Kf, Vf, base, 1, tid);
    CP_COMMIT();

    CP_WAIT1();
    __syncthreads();

    const uint32_t lrow = (lane & 7) + ((lane >> 3) & 1) * 8;
    const uint32_t kb16 = ((lane >> 4) & 1) * 16;
    uint32_t qfh[4][4], qfl[4][4];
#pragma unroll
    for (int ks = 0; ks < 4; ks++) {
        uint32_t a = sQ + (wid * 16 + lrow) * AP + ks * 32 + kb16;
        ldsm4(qfh[ks], a);
        ldsm4(qfl[ks], a + QT_B);
    }

    float oacc[8][4];
#pragma unroll
    for (int nj = 0; nj < 8; nj++)
#pragma unroll
        for (int q = 0; q < 4; q++) oacc[nj][q] = 0.f;
    float m0 = NINF, m1 = NINF, l0 = 0.f, l1 = 0.f;

    const int r0 = qb * 128 + wid * 16 + g;
    const int r1 = r0 + 8;

    const uint32_t vrow = (lane & 7) + ((lane >> 4) & 1) * 8;
    const uint32_t vb16 = ((lane >> 3) & 1) * 16;

    for (int kb = 0; kb < nkb; kb++) {
        if (kb + 1 < nkb) CP_WAIT1(); else CP_WAIT0();
        __syncthreads();

        const uint32_t sK = sKV + (kb & 1) * ASTG_B;
        const uint32_t sV = sK + KT_B;

        // ---- S = Qh*K + Ql*K (fp16 2-term) ----
        float sf[8][4];
#pragma unroll
        for (int nj = 0; nj < 8; nj++)
#pragma unroll
            for (int q = 0; q < 4; q++) sf[nj][q] = 0.f;

#pragma unroll
        for (int ks = 0; ks < 4; ks++) {
#pragma unroll
            for (int ntp = 0; ntp < 2; ntp++) {
                uint32_t kfr[2][4];
#pragma unroll
                for (int nt2 = 0; nt2 < 2; nt2++) {
                    uint32_t ba = sK + ((ntp * 2 + nt2) * 16 + lrow) * AP + ks * 32 + kb16;
                    ldsm4(kfr[nt2], ba);
                }
#pragma unroll
                for (int term = 0; term < 2; term++) {
                    const uint32_t* a = term ? qfl[ks] : qfh[ks];
#pragma unroll
                    for (int nt2 = 0; nt2 < 2; nt2++) {
#pragma unroll
                        for (int sel = 0; sel < 2; sel++) {
                            const int nj = (ntp * 2 + nt2) * 2 + sel;
                            mma16816h(sf[nj], a, kfr[nt2][sel], kfr[nt2][sel + 2]);
                        }
                    }
                }
            }
        }

        // ---- causal mask ----
        if (kb >= 2 * qb) {
#pragma unroll
            for (int nj = 0; nj < 8; nj++) {
                int c0 = kb * 64 + nj * 8 + 2 * t;
                if (c0 > r0)     sf[nj][0] = NINF;
                if (c0 + 1 > r0) sf[nj][1] = NINF;
                if (c0 > r1)     sf[nj][2] = NINF;
                if (c0 + 1 > r1) sf[nj][3] = NINF;
            }
        }

        // ---- online softmax (base-2 domain) ----
        float mx0 = sf[0][0], mx1 = sf[0][2];
#pragma unroll
        for (int nj = 0; nj < 8; nj++) {
            mx0 = fmaxf(mx0, fmaxf(sf[nj][0], sf[nj][1]));
            mx1 = fmaxf(mx1, fmaxf(sf[nj][2], sf[nj][3]));
        }
        mx0 = fmaxf(mx0, __shfl_xor_sync(0xffffffffu, mx0, 1));
        mx0 = fmaxf(mx0, __shfl_xor_sync(0xffffffffu, mx0, 2));
        mx1 = fmaxf(mx1, __shfl_xor_sync(0xffffffffu, mx1, 1));
        mx1 = fmaxf(mx1, __shfl_xor_sync(0xffffffffu, mx1, 2));
        float mn0 = fmaxf(m0, mx0), mn1 = fmaxf(m1, mx1);
        float al0 = ex2(m0 - mn0), al1 = ex2(m1 - mn1);
        m0 = mn0; m1 = mn1;

        float s0 = 0.f, s1 = 0.f;
#pragma unroll
        for (int nj = 0; nj < 8; nj++) {
            sf[nj][0] = ex2(sf[nj][0] - m0);
            sf[nj][1] = ex2(sf[nj][1] - m0);
            sf[nj][2] = ex2(sf[nj][2] - m1);
            sf[nj][3] = ex2(sf[nj][3] - m1);
            s0 += sf[nj][0] + sf[nj][1];
            s1 += sf[nj][2] + sf[nj][3];
        }
        s0 += __shfl_xor_sync(0xffffffffu, s0, 1);
        s0 += __shfl_xor_sync(0xffffffffu, s0, 2);
        s1 += __shfl_xor_sync(0xffffffffu, s1, 1);
        s1 += __shfl_xor_sync(0xffffffffu, s1, 2);
        l0 = l0 * al0 + s0;
        l1 = l1 * al1 + s1;

#pragma unroll
        for (int nj = 0; nj < 8; nj++) {
            oacc[nj][0] *= al0; oacc[nj][1] *= al0;
            oacc[nj][2] *= al1; oacc[nj][3] *= al1;
        }

        // ---- O += P * V  (fp16 single-term) ----
#pragma unroll
        for (int ks = 0; ks < 4; ks++) {
            uint32_t pa[4];
            pa[0] = packhf(sf[2 * ks][0],     sf[2 * ks][1]);
            pa[1] = packhf(sf[2 * ks][2],     sf[2 * ks][3]);
            pa[2] = packhf(sf[2 * ks + 1][0], sf[2 * ks + 1][1]);
            pa[3] = packhf(sf[2 * ks + 1][2], sf[2 * ks + 1][3]);
#pragma unroll
            for (int ntp = 0; ntp < 2; ntp++) {
                uint32_t vfr[2][4];
#pragma unroll
                for (int nt2 = 0; nt2 < 2; nt2++) {
                    uint32_t va = sV + (ks * 16 + vrow) * AP + (ntp * 2 + nt2) * 32 + vb16;
                    ldsm4t(vfr[nt2], va);
                }
#pragma unroll
                for (int nt2 = 0; nt2 < 2; nt2++) {
#pragma unroll
                    for (int sel = 0; sel < 2; sel++) {
                        const int nj = (ntp * 2 + nt2) * 2 + sel;
                        mma16816h(oacc[nj], pa, vfr[nt2][sel], vfr[nt2][sel + 2]);
                    }
                }
            }
        }
        __syncthreads();

        if (kb + 2 < nkb) {
            issue_kv(sKV + (kb & 1) * ASTG_B, Kf, Vf, base, kb + 2, tid);
            CP_COMMIT();
        }
    }

    // ---- epilogue: fp16 AO at [b*S+s][h*64+dk] ----
    const float inv0 = 1.0f / l0;
    const float inv1 = 1.0f / l1;
    const int b = bh >> 4, h = bh & 15;
    const size_t row0 = (size_t)(b * SS + r0) * DM;
    const size_t row1 = (size_t)(b * SS + r1) * DM;
#pragma unroll
    for (int nj = 0; nj < 8; nj++) {
        const int e = h * 64 + nj * 8 + 2 * t;
        *(uint32_t*)&AOf[row0 + e] = packhf(oacc[nj][0] * inv0, oacc[nj][1] * inv0);
        *(uint32_t*)&AOf[row1 + e] = packhf(oacc[nj][2] * inv1, oacc[nj][3] * inv1);
    }
}

// ---------------------------------------------------------------------------
extern "C" void kernel_launch(void* const* d_in, const int* in_sizes, int n_in,
                              void* d_out, int out_size)
{
    const float* x  = (const float*)d_in[0];
    const float* Wq = (const float*)d_in[1];
    const float* Wk = (const float*)d_in[2];
    const float* Wv = (const float*)d_in[3];
    const float* Wo = (const float*)d_in[4];
    const int*   tp = (const int*)  d_in[5];
    float* out = (float*)d_out;

    float* gRope;
    __half *xf, *wf, *vf, *aof, *qh, *ql, *kf;
    cudaGetSymbolAddress((void**)&gRope, g_rope);
    cudaGetSymbolAddress((void**)&xf,  g_xf);
    cudaGetSymbolAddress((void**)&wf,  g_wf);
    cudaGetSymbolAddress((void**)&vf,  g_vf);
    cudaGetSymbolAddress((void**)&aof, g_aof);
    cudaGetSymbolAddress((void**)&qh,  g_Qh);
    cudaGetSymbolAddress((void**)&ql,  g_Ql);
    cudaGetSymbolAddress((void**)&kf,  g_Kf);

    cudaFuncSetAttribute(gemm_h,   cudaFuncAttributeMaxDynamicSharedMemorySize, GSMEM);
    cudaFuncSetAttribute(attn_mma, cudaFuncAttributeMaxDynamicSharedMemorySize, ASMEM);

    const int nx4 = MTOT * DM / 4;
    const int nw4 = DM * DM / 4;
    cvt_kernel<<<nx4 / 256, 256>>>(x, xf, nx4);
    dim3 wgrid(nw4 / 256, 4);
    cvt_w_kernel<<<wgrid, 256>>>(Wq, Wk, Wv, Wo, wf);
    rope_init_kernel<<<SS * 32 / 256, 256>>>(tp, gRope);

    dim3 qkvgrid(MTOT / 128, 24);   // (64, 24)
    gemm_h<<<qkvgrid, 256, GSMEM>>>(xf, wf, nullptr,
                                    qh, ql, kf, vf, gRope, 0);

    attn_mma<<<1024, 256, ASMEM>>>(qh, ql, kf, vf, aof);

    dim3 wogrid(MTOT / 128, 8);     // (64, 8)
    gemm_h<<<wogrid, 256, GSMEM>>>(aof, wf, out,
                                   qh, ql, kf, vf, gRope, 1);
}

// round 16
// speedup vs baseline: 1.2570x; 1.1027x over previous
#include <cuda_runtime.h>
#include <cuda_fp16.h>
#include <math.h>
#include <math_constants.h>
#include <cstdint>

#define BB 4
#define SS 2048
#define DM 1024
#define HH 16
#define DKK 64
#define MTOT (BB*SS)   // 8192

// ---------------- scratch (allocation-free) ----------------
__device__ __half g_xf[(size_t)MTOT*DM];
__device__ __half g_wf[(size_t)4*DM*DM];
__device__ __half g_vf[(size_t)BB*HH*SS*DKK];
__device__ __half g_aof[(size_t)MTOT*DM];
__device__ __half g_Qf[(size_t)BB*HH*SS*DKK];
__device__ __half g_Kf[(size_t)BB*HH*SS*DKK];
__device__ float g_rope[SS*64];   // [s][0..31]=cos, [s][32..63]=sin

#define ASCALE 0.1803368801111244f   // 1/sqrt(64)*log2(e)

// ---------------- PTX helpers ----------------
__device__ __forceinline__ uint32_t smem_to_u32(const void* p) {
    uint32_t a;
    asm("{ .reg .u64 t; cvta.to.shared.u64 t, %1; cvt.u32.u64 %0, t; }"
        : "=r"(a) : "l"(p));
    return a;
}
__device__ __forceinline__ void cp16(uint32_t dst, const void* src) {
    asm volatile("cp.async.cg.shared.global [%0], [%1], 16;"
                 :: "r"(dst), "l"(src) : "memory");
}
#define CP_COMMIT() asm volatile("cp.async.commit_group;" ::: "memory")
#define CP_WAIT1()  asm volatile("cp.async.wait_group 1;"  ::: "memory")
#define CP_WAIT0()  asm volatile("cp.async.wait_group 0;"  ::: "memory")

__device__ __forceinline__ void ldsm4(uint32_t* r, uint32_t addr) {
    asm volatile("ldmatrix.sync.aligned.m8n8.x4.shared.b16 {%0,%1,%2,%3}, [%4];"
                 : "=r"(r[0]), "=r"(r[1]), "=r"(r[2]), "=r"(r[3]) : "r"(addr));
}
__device__ __forceinline__ void ldsm4t(uint32_t* r, uint32_t addr) {
    asm volatile("ldmatrix.sync.aligned.m8n8.x4.trans.shared.b16 {%0,%1,%2,%3}, [%4];"
                 : "=r"(r[0]), "=r"(r[1]), "=r"(r[2]), "=r"(r[3]) : "r"(addr));
}
__device__ __forceinline__ void mma16816h(float* d, const uint32_t* a,
                                          uint32_t b0, uint32_t b1) {
    asm volatile("mma.sync.aligned.m16n8k16.row.col.f32.f16.f16.f32 "
                 "{%0,%1,%2,%3}, {%4,%5,%6,%7}, {%8,%9}, {%0,%1,%2,%3};"
                 : "+f"(d[0]), "+f"(d[1]), "+f"(d[2]), "+f"(d[3])
                 : "r"(a[0]), "r"(a[1]), "r"(a[2]), "r"(a[3]), "r"(b0), "r"(b1));
}
__device__ __forceinline__ float ex2(float x) {
    float y;
    asm("ex2.approx.f32 %0, %1;" : "=f"(y) : "f"(x));
    return y;
}
__device__ __forceinline__ uint32_t packhf(float lo, float hi) {
    uint32_t r;
    asm("cvt.rn.f16x2.f32 %0, %1, %2;" : "=r"(r) : "f"(hi), "f"(lo));
    return r;
}

// ---------------------------------------------------------------------------
// fp32 -> fp16 conversions
// ---------------------------------------------------------------------------
__global__ void cvt_kernel(const float* __restrict__ src, __half* __restrict__ dst, int n4)
{
    int i = blockIdx.x * blockDim.x + threadIdx.x;
    if (i >= n4) return;
    float4 v = ((const float4*)src)[i];
    ((uint2*)dst)[i] = make_uint2(packhf(v.x, v.y), packhf(v.z, v.w));
}

__global__ void cvt_w_kernel(const float* __restrict__ w0, const float* __restrict__ w1,
                             const float* __restrict__ w2, const float* __restrict__ w3,
                             __half* __restrict__ dst)
{
    const int wsel = blockIdx.y;
    const float* src = (wsel == 0) ? w0 : (wsel == 1) ? w1 : (wsel == 2) ? w2 : w3;
    size_t off = (size_t)wsel * (DM * DM / 4);
    int i = blockIdx.x * blockDim.x + threadIdx.x;
    float4 v = ((const float4*)src)[i];
    ((uint2*)dst)[off + i] = make_uint2(packhf(v.x, v.y), packhf(v.z, v.w));
}

__global__ void rope_init_kernel(const int* __restrict__ tokpos, float* __restrict__ rope)
{
    int idx = blockIdx.x * blockDim.x + threadIdx.x;
    int s = idx >> 5, p = idx & 31;
    float fr = (float)exp2(-(double)p * (13.287712379549449 / 32.0));
    float ang = (float)tokpos[s] * fr;
    float sn, cs;
    sincosf(ang, &sn, &cs);
    rope[s * 64 + p] = cs;
    rope[s * 64 + 32 + p] = sn;
}

// ---------------------------------------------------------------------------
// fp16 single-term GEMM, 2-stage cp.async (validated round-13 structure).
// wsel 0: RoPE*ASCALE -> Q fp16; 1: RoPE -> K fp16; 2: -> V fp16; 3: fp32 out.
// ---------------------------------------------------------------------------
#define GP      40
#define TILE_B  (128*GP*2)         // 10240 bytes
#define STAGE_B (2*TILE_B)         // 20480 (A | B)
#define GSMEM   (2*STAGE_B)        // 40960

__device__ __forceinline__ void issue_stage(uint32_t sdst,
    const __half* __restrict__ A, const __half* __restrict__ B,
    int m0, int n0, int kc, int tid)
{
    const int colb = kc * 64;
#pragma unroll
    for (int it = 0; it < 2; it++) {
        int idx = tid + it * 256;
        int row = idx >> 2;
        int ch  = (idx & 3) * 16;
        uint32_t soff = row * 80 + ch;
        cp16(sdst + soff,          (const char*)(A + (size_t)(m0 + row) * DM) + colb + ch);
        cp16(sdst + TILE_B + soff, (const char*)(B + (size_t)(n0 + row) * DM) + colb + ch);
    }
}

__global__ __launch_bounds__(256, 2)
void gemm_h(const __half* __restrict__ A, const __half* __restrict__ WBase,
            float* __restrict__ out,
            __half* __restrict__ qf, __half* __restrict__ kf, __half* __restrict__ vf,
            const float* __restrict__ rope, int wo)
{
    extern __shared__ char smc[];
    const uint32_t sbase = smem_to_u32(smc);

    const int tid  = threadIdx.x;
    const int wid  = tid >> 5;
    const int lane = tid & 31;
    const int m0 = blockIdx.x * 128;
    const int by = blockIdx.y;
    const int wsel = wo ? 3 : (by >> 3);
    const int n0 = wo ? by * 128 : (by & 7) * 128;
    const __half* B = WBase + (size_t)wsel * DM * DM;

    const int wm = (wid & 3) * 32;
    const int wn = (wid >> 2) * 64;

    float acc[2][8][4];
#pragma unroll
    for (int i = 0; i < 2; i++)
#pragma unroll
        for (int j = 0; j < 8; j++)
#pragma unroll
            for (int q = 0; q < 4; q++) acc[i][j][q] = 0.f;

    const uint32_t lrow = (lane & 7) + ((lane >> 3) & 1) * 8;
    const uint32_t kbl  = ((lane >> 4) & 1) * 16;

    issue_stage(sbase, A, B, m0, n0, 0, tid);
    CP_COMMIT();

    const int NKC = DM / 32;   // 32
    for (int kc = 0; kc < NKC; kc++) {
        CP_WAIT0();
        __syncthreads();
        if (kc + 1 < NKC) {
            issue_stage(sbase + ((kc + 1) & 1) * STAGE_B, A, B, m0, n0, kc + 1, tid);
            CP_COMMIT();
        }

        const uint32_t sb = sbase + (kc & 1) * STAGE_B;
#pragma unroll
        for (int ks = 0; ks < 2; ks++) {
            const uint32_t kb = ks * 32 + kbl;
            uint32_t a0[4], a1[4];
            const uint32_t aadr = sb + (wm + lrow) * 80 + kb;
            ldsm4(a0, aadr);
            ldsm4(a1, aadr + 16 * 80);
#pragma unroll
            for (int nb = 0; nb < 4; nb++) {
                uint32_t bf[4];
                const uint32_t badr = sb + TILE_B + (wn + nb * 16 + lrow) * 80 + kb;
                ldsm4(bf, badr);
#pragma unroll
                for (int sel = 0; sel < 2; sel++) {
                    const int nj = nb * 2 + sel;
                    mma16816h(acc[0][nj], a0, bf[sel], bf[sel + 2]);
                    mma16816h(acc[1][nj], a1, bf[sel], bf[sel + 2]);
                }
            }
        }
    }

    // ---- epilogue ----
    const int g = lane >> 2;
    const int t2 = (lane & 3) * 2;
#pragma unroll
    for (int mi = 0; mi < 2; mi++) {
#pragma unroll
        for (int half = 0; half < 2; half++) {
            const int r = m0 + wm + mi * 16 + half * 8 + g;
            const int b = r >> 11;
            const int s = r & 2047;
#pragma unroll
            for (int nj = 0; nj < 8; nj++) {
                const int e = n0 + wn + nj * 8 + t2;
                float d0 = acc[mi][nj][half * 2 + 0];
                float d1 = acc[mi][nj][half * 2 + 1];
                if (wsel == 3) {
                    *(float2*)&out[(size_t)r * DM + e] = make_float2(d0, d1);
                } else {
                    const int h  = e >> 6;
                    const int dk = e & 63;
                    size_t idx = ((size_t)(b * HH + h) * SS + s) * DKK + dk;
                    if (wsel == 2) {
                        *(uint32_t*)&vf[idx] = packhf(d0, d1);
                    } else {
                        const int p = dk >> 1;
                        float cs = __ldg(&rope[s * 64 + p]);
                        float sn = __ldg(&rope[s * 64 + 32 + p]);
                        float r0 = d0 * cs - d1 * sn;
                        float r1 = d0 * sn + d1 * cs;
                        if (wsel == 0) {
                            r0 *= ASCALE; r1 *= ASCALE;
                            *(uint32_t*)&qf[idx] = packhf(r0, r1);
                        } else {
                            *(uint32_t*)&kf[idx] = packhf(r0, r1);
                        }
                    }
                }
            }
        }
    }
}

// ---------------------------------------------------------------------------
// Flash attention: S = Q*K (fp16 single), PV fp16 single.
// 2-stage KV (Kf | Vf per stage), 2 CTAs/SM.
// ---------------------------------------------------------------------------
#define AP      144
#define QT_B    (128*AP)      // 18432
#define KT_B    (64*AP)       // 9216
#define ASTG_B  (2*KT_B)      // 18432
#define ASMEM   (QT_B + 2*ASTG_B)   // 55296

__device__ __forceinline__ void issue_kv(uint32_t dst,
    const __half* __restrict__ Kf, const __half* __restrict__ Vf,
    size_t base, int kb, int tid)
{
#pragma unroll
    for (int it = 0; it < 4; it++) {
        int f   = tid + it * 256;       // 0..1023
        int ten = f >> 9;               // 0,1
        int row = (f >> 3) & 63;
        int ch  = f & 7;
        const __half* sp = (ten ? Vf : Kf)
            + base + (size_t)(kb * 64 + row) * DKK + ch * 8;
        cp16(dst + ten * KT_B + row * AP + ch * 16, sp);
    }
}

__global__ __launch_bounds__(256, 2)
void attn_mma(const __half* __restrict__ Qf,
              const __half* __restrict__ Kf, const __half* __restrict__ Vf,
              __half* __restrict__ AOf)
{
    extern __shared__ char smc[];
    const uint32_t sb = smem_to_u32(smc);
    const uint32_t sQ  = sb;
    const uint32_t sKV = sb + QT_B;

    const int tid  = threadIdx.x;
    const int wid  = tid >> 5;
    const int lane = tid & 31;
    const int g = lane >> 2;
    const int t = lane & 3;

    const int qb = 15 - (blockIdx.x >> 6);    // heavy q-blocks first
    const int bh = blockIdx.x & 63;
    const size_t base = (size_t)bh * SS * DKK;
    const int nkb = 2 * qb + 2;

    const float NINF = __int_as_float(0xff800000);

#pragma unroll
    for (int it = 0; it < 4; it++) {
        int f   = tid + it * 256;       // 0..1023
        int row = f >> 3;
        int ch  = f & 7;
        const __half* sp = Qf + base + (size_t)(qb * 128 + row) * DKK + ch * 8;
        cp16(sQ + row * AP + ch * 16, sp);
    }
    issue_kv(sKV, Kf, Vf, base, 0, tid);
    CP_COMMIT();
    issue_kv(sKV + ASTG_B, Kf, Vf, base, 1, tid);
    CP_COMMIT();

    CP_WAIT1();
    __syncthreads();

    const uint32_t lrow = (lane & 7) + ((lane >> 3) & 1) * 8;
    const uint32_t kb16 = ((lane >> 4) & 1) * 16;
    uint32_t qf[4][4];
#pragma unroll
    for (int ks = 0; ks < 4; ks++) {
        uint32_t a = sQ + (wid * 16 + lrow) * AP + ks * 32 + kb16;
        ldsm4(qf[ks], a);
    }

    float oacc[8][4];
#pragma unroll
    for (int nj = 0; nj < 8; nj++)
#pragma unroll
        for (int q = 0; q < 4; q++) oacc[nj][q] = 0.f;
    float m0 = NINF, m1 = NINF, l0 = 0.f, l1 = 0.f;

    const int r0 = qb * 128 + wid * 16 + g;
    const int r1 = r0 + 8;

    const uint32_t vrow = (lane & 7) + ((lane >> 4) & 1) * 8;
    const uint32_t vb16 = ((lane >> 3) & 1) * 16;

    for (int kb = 0; kb < nkb; kb++) {
        if (kb + 1 < nkb) CP_WAIT1(); else CP_WAIT0();
        __syncthreads();

        const uint32_t sK = sKV + (kb & 1) * ASTG_B;
        const uint32_t sV = sK + KT_B;

        // ---- S = Q*K (fp16 single-term) ----
        float sf[8][4];
#pragma unroll
        for (int nj = 0; nj < 8; nj++)
#pragma unroll
            for (int q = 0; q < 4; q++) sf[nj][q] = 0.f;

#pragma unroll
        for (int ks = 0; ks < 4; ks++) {
#pragma unroll
            for (int ntp = 0; ntp < 2; ntp++) {
                uint32_t kfr[2][4];
#pragma unroll
                for (int nt2 = 0; nt2 < 2; nt2++) {
                    uint32_t ba = sK + ((ntp * 2 + nt2) * 16 + lrow) * AP + ks * 32 + kb16;
                    ldsm4(kfr[nt2], ba);
                }
#pragma unroll
                for (int nt2 = 0; nt2 < 2; nt2++) {
#pragma unroll
                    for (int sel = 0; sel < 2; sel++) {
                        const int nj = (ntp * 2 + nt2) * 2 + sel;
                        mma16816h(sf[nj], qf[ks], kfr[nt2][sel], kfr[nt2][sel + 2]);
                    }
                }
            }
        }

        // ---- causal mask ----
        if (kb >= 2 * qb) {
#pragma unroll
            for (int nj = 0; nj < 8; nj++) {
                int c0 = kb * 64 + nj * 8 + 2 * t;
                if (c0 > r0)     sf[nj][0] = NINF;
                if (c0 + 1 > r0) sf[nj][1] = NINF;
                if (c0 > r1)     sf[nj][2] = NINF;
                if (c0 + 1 > r1) sf[nj][3] = NINF;
            }
        }

        // ---- online softmax (base-2 domain) ----
        float mx0 = sf[0][0], mx1 = sf[0][2];
#pragma unroll
        for (int nj = 0; nj < 8; nj++) {
            mx0 = fmaxf(mx0, fmaxf(sf[nj][0], sf[nj][1]));
            mx1 = fmaxf(mx1, fmaxf(sf[nj][2], sf[nj][3]));
        }
        mx0 = fmaxf(mx0, __shfl_xor_sync(0xffffffffu, mx0, 1));
        mx0 = fmaxf(mx0, __shfl_xor_sync(0xffffffffu, mx0, 2));
        mx1 = fmaxf(mx1, __shfl_xor_sync(0xffffffffu, mx1, 1));
        mx1 = fmaxf(mx1, __shfl_xor_sync(0xffffffffu, mx1, 2));
        float mn0 = fmaxf(m0, mx0), mn1 = fmaxf(m1, mx1);
        float al0 = ex2(m0 - mn0), al1 = ex2(m1 - mn1);
        m0 = mn0; m1 = mn1;

        float s0 = 0.f, s1 = 0.f;
#pragma unroll
        for (int nj = 0; nj < 8; nj++) {
            sf[nj][0] = ex2(sf[nj][0] - m0);
            sf[nj][1] = ex2(sf[nj][1] - m0);
            sf[nj][2] = ex2(sf[nj][2] - m1);
            sf[nj][3] = ex2(sf[nj][3] - m1);
            s0 += sf[nj][0] + sf[nj][1];
            s1 += sf[nj][2] + sf[nj][3];
        }
        s0 += __shfl_xor_sync(0xffffffffu, s0, 1);
        s0 += __shfl_xor_sync(0xffffffffu, s0, 2);
        s1 += __shfl_xor_sync(0xffffffffu, s1, 1);
        s1 += __shfl_xor_sync(0xffffffffu, s1, 2);
        l0 = l0 * al0 + s0;
        l1 = l1 * al1 + s1;

#pragma unroll
        for (int nj = 0; nj < 8; nj++) {
            oacc[nj][0] *= al0; oacc[nj][1] *= al0;
            oacc[nj][2] *= al1; oacc[nj][3] *= al1;
        }

        // ---- O += P * V  (fp16 single-term) ----
#pragma unroll
        for (int ks = 0; ks < 4; ks++) {
            uint32_t pa[4];
            pa[0] = packhf(sf[2 * ks][0],     sf[2 * ks][1]);
            pa[1] = packhf(sf[2 * ks][2],     sf[2 * ks][3]);
            pa[2] = packhf(sf[2 * ks + 1][0], sf[2 * ks + 1][1]);
            pa[3] = packhf(sf[2 * ks + 1][2], sf[2 * ks + 1][3]);
#pragma unroll
            for (int ntp = 0; ntp < 2; ntp++) {
                uint32_t vfr[2][4];
#pragma unroll
                for (int nt2 = 0; nt2 < 2; nt2++) {
                    uint32_t va = sV + (ks * 16 + vrow) * AP + (ntp * 2 + nt2) * 32 + vb16;
                    ldsm4t(vfr[nt2], va);
                }
#pragma unroll
                for (int nt2 = 0; nt2 < 2; nt2++) {
#pragma unroll
                    for (int sel = 0; sel < 2; sel++) {
                        const int nj = (ntp * 2 + nt2) * 2 + sel;
                        mma16816h(oacc[nj], pa, vfr[nt2][sel], vfr[nt2][sel + 2]);
                    }
                }
            }
        }
        __syncthreads();

        if (kb + 2 < nkb) {
            issue_kv(sKV + (kb & 1) * ASTG_B, Kf, Vf, base, kb + 2, tid);
            CP_COMMIT();
        }
    }

    // ---- epilogue: fp16 AO at [b*S+s][h*64+dk] ----
    const float inv0 = 1.0f / l0;
    const float inv1 = 1.0f / l1;
    const int b = bh >> 4, h = bh & 15;
    const size_t row0 = (size_t)(b * SS + r0) * DM;
    const size_t row1 = (size_t)(b * SS + r1) * DM;
#pragma unroll
    for (int nj = 0; nj < 8; nj++) {
        const int e = h * 64 + nj * 8 + 2 * t;
        *(uint32_t*)&AOf[row0 + e] = packhf(oacc[nj][0] * inv0, oacc[nj][1] * inv0);
        *(uint32_t*)&AOf[row1 + e] = packhf(oacc[nj][2] * inv1, oacc[nj][3] * inv1);
    }
}

// ---------------------------------------------------------------------------
extern "C" void kernel_launch(void* const* d_in, const int* in_sizes, int n_in,
                              void* d_out, int out_size)
{
    const float* x  = (const float*)d_in[0];
    const float* Wq = (const float*)d_in[1];
    const float* Wk = (const float*)d_in[2];
    const float* Wv = (const float*)d_in[3];
    const float* Wo = (const float*)d_in[4];
    const int*   tp = (const int*)  d_in[5];
    float* out = (float*)d_out;

    float* gRope;
    __half *xf, *wf, *vf, *aof, *qf, *kf;
    cudaGetSymbolAddress((void**)&gRope, g_rope);
    cudaGetSymbolAddress((void**)&xf,  g_xf);
    cudaGetSymbolAddress((void**)&wf,  g_wf);
    cudaGetSymbolAddress((void**)&vf,  g_vf);
    cudaGetSymbolAddress((void**)&aof, g_aof);
    cudaGetSymbolAddress((void**)&qf,  g_Qf);
    cudaGetSymbolAddress((void**)&kf,  g_Kf);

    cudaFuncSetAttribute(gemm_h,   cudaFuncAttributeMaxDynamicSharedMemorySize, GSMEM);
    cudaFuncSetAttribute(attn_mma, cudaFuncAttributeMaxDynamicSharedMemorySize, ASMEM);

    const int nx4 = MTOT * DM / 4;
    const int nw4 = DM * DM / 4;
    cvt_kernel<<<nx4 / 256, 256>>>(x, xf, nx4);
    dim3 wgrid(nw4 / 256, 4);
    cvt_w_kernel<<<wgrid, 256>>>(Wq, Wk, Wv, Wo, wf);
    rope_init_kernel<<<SS * 32 / 256, 256>>>(tp, gRope);

    dim3 qkvgrid(MTOT / 128, 24);   // (64, 24)
    gemm_h<<<qkvgrid, 256, GSMEM>>>(xf, wf, nullptr, qf, kf, vf, gRope, 0);

    attn_mma<<<1024, 256, ASMEM>>>(qf, kf, vf, aof);

    dim3 wogrid(MTOT / 128, 8);     // (64, 8)
    gemm_h<<<wogrid, 256, GSMEM>>>(aof, wf, out, qf, kf, vf, gRope, 1);
}

// round 17
// speedup vs baseline: 1.3250x; 1.0541x over previous
#include <cuda_runtime.h>
#include <cuda_fp16.h>
#include <math.h>
#include <math_constants.h>
#include <cstdint>

#define BB 4
#define SS 2048
#define DM 1024
#define HH 16
#define DKK 64
#define MTOT (BB*SS)   // 8192

// ---------------- scratch (allocation-free) ----------------
__device__ __half g_xf[(size_t)MTOT*DM];
__device__ __half g_wf[(size_t)4*DM*DM];
__device__ __half g_vf[(size_t)BB*HH*SS*DKK];
__device__ __half g_aof[(size_t)MTOT*DM];
__device__ __half g_Qf[(size_t)BB*HH*SS*DKK];
__device__ __half g_Kf[(size_t)BB*HH*SS*DKK];
__device__ float g_rope[SS*64];   // [s][0..31]=cos, [s][32..63]=sin

#define ASCALE 0.1803368801111244f   // 1/sqrt(64)*log2(e)

// ---------------- PTX helpers ----------------
__device__ __forceinline__ uint32_t smem_to_u32(const void* p) {
    uint32_t a;
    asm("{ .reg .u64 t; cvta.to.shared.u64 t, %1; cvt.u32.u64 %0, t; }"
        : "=r"(a) : "l"(p));
    return a;
}
__device__ __forceinline__ void cp16(uint32_t dst, const void* src) {
    asm volatile("cp.async.cg.shared.global [%0], [%1], 16;"
                 :: "r"(dst), "l"(src) : "memory");
}
#define CP_COMMIT() asm volatile("cp.async.commit_group;" ::: "memory")
#define CP_WAIT1()  asm volatile("cp.async.wait_group 1;"  ::: "memory")
#define CP_WAIT0()  asm volatile("cp.async.wait_group 0;"  ::: "memory")

__device__ __forceinline__ void ldsm4(uint32_t* r, uint32_t addr) {
    asm volatile("ldmatrix.sync.aligned.m8n8.x4.shared.b16 {%0,%1,%2,%3}, [%4];"
                 : "=r"(r[0]), "=r"(r[1]), "=r"(r[2]), "=r"(r[3]) : "r"(addr));
}
__device__ __forceinline__ void ldsm4t(uint32_t* r, uint32_t addr) {
    asm volatile("ldmatrix.sync.aligned.m8n8.x4.trans.shared.b16 {%0,%1,%2,%3}, [%4];"
                 : "=r"(r[0]), "=r"(r[1]), "=r"(r[2]), "=r"(r[3]) : "r"(addr));
}
__device__ __forceinline__ void mma16816h(float* d, const uint32_t* a,
                                          uint32_t b0, uint32_t b1) {
    asm volatile("mma.sync.aligned.m16n8k16.row.col.f32.f16.f16.f32 "
                 "{%0,%1,%2,%3}, {%4,%5,%6,%7}, {%8,%9}, {%0,%1,%2,%3};"
                 : "+f"(d[0]), "+f"(d[1]), "+f"(d[2]), "+f"(d[3])
                 : "r"(a[0]), "r"(a[1]), "r"(a[2]), "r"(a[3]), "r"(b0), "r"(b1));
}
__device__ __forceinline__ float ex2(float x) {
    float y;
    asm("ex2.approx.f32 %0, %1;" : "=f"(y) : "f"(x));
    return y;
}
__device__ __forceinline__ uint32_t packhf(float lo, float hi) {
    uint32_t r;
    asm("cvt.rn.f16x2.f32 %0, %1, %2;" : "=r"(r) : "f"(hi), "f"(lo));
    return r;
}

// ---------------------------------------------------------------------------
// fp32 -> fp16 conversions
// ---------------------------------------------------------------------------
__global__ void cvt_kernel(const float* __restrict__ src, __half* __restrict__ dst, int n4)
{
    int i = blockIdx.x * blockDim.x + threadIdx.x;
    if (i >= n4) return;
    float4 v = ((const float4*)src)[i];
    ((uint2*)dst)[i] = make_uint2(packhf(v.x, v.y), packhf(v.z, v.w));
}

__global__ void cvt_w_kernel(const float* __restrict__ w0, const float* __restrict__ w1,
                             const float* __restrict__ w2, const float* __restrict__ w3,
                             __half* __restrict__ dst)
{
    const int wsel = blockIdx.y;
    const float* src = (wsel == 0) ? w0 : (wsel == 1) ? w1 : (wsel == 2) ? w2 : w3;
    size_t off = (size_t)wsel * (DM * DM / 4);
    int i = blockIdx.x * blockDim.x + threadIdx.x;
    float4 v = ((const float4*)src)[i];
    ((uint2*)dst)[off + i] = make_uint2(packhf(v.x, v.y), packhf(v.z, v.w));
}

__global__ void rope_init_kernel(const int* __restrict__ tokpos, float* __restrict__ rope)
{
    int idx = blockIdx.x * blockDim.x + threadIdx.x;
    int s = idx >> 5, p = idx & 31;
    float fr = (float)exp2(-(double)p * (13.287712379549449 / 32.0));
    float ang = (float)tokpos[s] * fr;
    float sn, cs;
    sincosf(ang, &sn, &cs);
    rope[s * 64 + p] = cs;
    rope[s * 64 + 32 + p] = sn;
}

// ---------------------------------------------------------------------------
// fp16 single-term GEMM, BK=64, 2-stage cp.async, 2 CTAs/SM, pitch-144 smem.
// wsel 0: RoPE*ASCALE -> Q fp16; 1: RoPE -> K fp16; 2: -> V fp16; 3: fp32 out.
// ---------------------------------------------------------------------------
#define GPP     144                // smem row pitch (bytes) for 64 halves/row
#define TILE_B  (128*GPP)          // 18432 bytes
#define STAGE_B (2*TILE_B)         // 36864 (A | B)
#define GSMEM   (2*STAGE_B)        // 73728

__device__ __forceinline__ void issue_stage(uint32_t sdst,
    const __half* __restrict__ A, const __half* __restrict__ B,
    int m0, int n0, int kc, int tid)
{
    const int colb = kc * 128;     // byte offset of 64-wide k-chunk
#pragma unroll
    for (int it = 0; it < 4; it++) {
        int idx = tid + it * 256;          // 0..1023
        int row = idx >> 3;
        int ch  = (idx & 7) * 16;
        uint32_t soff = row * GPP + ch;
        cp16(sdst + soff,          (const char*)(A + (size_t)(m0 + row) * DM) + colb + ch);
        cp16(sdst + TILE_B + soff, (const char*)(B + (size_t)(n0 + row) * DM) + colb + ch);
    }
}

__global__ __launch_bounds__(256, 2)
void gemm_h(const __half* __restrict__ A, const __half* __restrict__ WBase,
            float* __restrict__ out,
            __half* __restrict__ qf, __half* __restrict__ kf, __half* __restrict__ vf,
            const float* __restrict__ rope, int wo)
{
    extern __shared__ char smc[];
    const uint32_t sbase = smem_to_u32(smc);

    const int tid  = threadIdx.x;
    const int wid  = tid >> 5;
    const int lane = tid & 31;
    const int m0 = blockIdx.x * 128;
    const int by = blockIdx.y;
    const int wsel = wo ? 3 : (by >> 3);
    const int n0 = wo ? by * 128 : (by & 7) * 128;
    const __half* B = WBase + (size_t)wsel * DM * DM;

    const int wm = (wid & 3) * 32;
    const int wn = (wid >> 2) * 64;

    float acc[2][8][4];
#pragma unroll
    for (int i = 0; i < 2; i++)
#pragma unroll
        for (int j = 0; j < 8; j++)
#pragma unroll
            for (int q = 0; q < 4; q++) acc[i][j][q] = 0.f;

    const uint32_t lrow = (lane & 7) + ((lane >> 3) & 1) * 8;
    const uint32_t kbl  = ((lane >> 4) & 1) * 16;

    issue_stage(sbase, A, B, m0, n0, 0, tid);
    CP_COMMIT();

    const int NKC = DM / 64;   // 16
    for (int kc = 0; kc < NKC; kc++) {
        CP_WAIT0();
        __syncthreads();
        if (kc + 1 < NKC) {
            issue_stage(sbase + ((kc + 1) & 1) * STAGE_B, A, B, m0, n0, kc + 1, tid);
            CP_COMMIT();
        }

        const uint32_t sb = sbase + (kc & 1) * STAGE_B;
#pragma unroll
        for (int ks = 0; ks < 4; ks++) {
            const uint32_t kb = ks * 32 + kbl;
            uint32_t a0[4], a1[4];
            const uint32_t aadr = sb + (wm + lrow) * GPP + kb;
            ldsm4(a0, aadr);
            ldsm4(a1, aadr + 16 * GPP);
#pragma unroll
            for (int nb = 0; nb < 4; nb++) {
                uint32_t bf[4];
                const uint32_t badr = sb + TILE_B + (wn + nb * 16 + lrow) * GPP + kb;
                ldsm4(bf, badr);
#pragma unroll
                for (int sel = 0; sel < 2; sel++) {
                    const int nj = nb * 2 + sel;
                    mma16816h(acc[0][nj], a0, bf[sel], bf[sel + 2]);
                    mma16816h(acc[1][nj], a1, bf[sel], bf[sel + 2]);
                }
            }
        }
    }

    // ---- epilogue ----
    const int g = lane >> 2;
    const int t2 = (lane & 3) * 2;
#pragma unroll
    for (int mi = 0; mi < 2; mi++) {
#pragma unroll
        for (int half = 0; half < 2; half++) {
            const int r = m0 + wm + mi * 16 + half * 8 + g;
            const int b = r >> 11;
            const int s = r & 2047;
#pragma unroll
            for (int nj = 0; nj < 8; nj++) {
                const int e = n0 + wn + nj * 8 + t2;
                float d0 = acc[mi][nj][half * 2 + 0];
                float d1 = acc[mi][nj][half * 2 + 1];
                if (wsel == 3) {
                    *(float2*)&out[(size_t)r * DM + e] = make_float2(d0, d1);
                } else {
                    const int h  = e >> 6;
                    const int dk = e & 63;
                    size_t idx = ((size_t)(b * HH + h) * SS + s) * DKK + dk;
                    if (wsel == 2) {
                        *(uint32_t*)&vf[idx] = packhf(d0, d1);
                    } else {
                        const int p = dk >> 1;
                        float cs = __ldg(&rope[s * 64 + p]);
                        float sn = __ldg(&rope[s * 64 + 32 + p]);
                        float r0 = d0 * cs - d1 * sn;
                        float r1 = d0 * sn + d1 * cs;
                        if (wsel == 0) {
                            r0 *= ASCALE; r1 *= ASCALE;
                            *(uint32_t*)&qf[idx] = packhf(r0, r1);
                        } else {
                            *(uint32_t*)&kf[idx] = packhf(r0, r1);
                        }
                    }
                }
            }
        }
    }
}

// ---------------------------------------------------------------------------
// Flash attention: S = Q*K (fp16 single), PV fp16 single.
// 2-stage KV (Kf | Vf per stage), 2 CTAs/SM. Unchanged (validated 412 µs).
// ---------------------------------------------------------------------------
#define AP      144
#define QT_B    (128*AP)      // 18432
#define KT_B    (64*AP)       // 9216
#define ASTG_B  (2*KT_B)      // 18432
#define ASMEM   (QT_B + 2*ASTG_B)   // 55296

__device__ __forceinline__ void issue_kv(uint32_t dst,
    const __half* __restrict__ Kf, const __half* __restrict__ Vf,
    size_t base, int kb, int tid)
{
#pragma unroll
    for (int it = 0; it < 4; it++) {
        int f   = tid + it * 256;       // 0..1023
        int ten = f >> 9;               // 0,1
        int row = (f >> 3) & 63;
        int ch  = f & 7;
        const __half* sp = (ten ? Vf : Kf)
            + base + (size_t)(kb * 64 + row) * DKK + ch * 8;
        cp16(dst + ten * KT_B + row * AP + ch * 16, sp);
    }
}

__global__ __launch_bounds__(256, 2)
void attn_mma(const __half* __restrict__ Qf,
              const __half* __restrict__ Kf, const __half* __restrict__ Vf,
              __half* __restrict__ AOf)
{
    extern __shared__ char smc[];
    const uint32_t sb = smem_to_u32(smc);
    const uint32_t sQ  = sb;
    const uint32_t sKV = sb + QT_B;

    const int tid  = threadIdx.x;
    const int wid  = tid >> 5;
    const int lane = tid & 31;
    const int g = lane >> 2;
    const int t = lane & 3;

    const int qb = 15 - (blockIdx.x >> 6);    // heavy q-blocks first
    const int bh = blockIdx.x & 63;
    const size_t base = (size_t)bh * SS * DKK;
    const int nkb = 2 * qb + 2;

    const float NINF = __int_as_float(0xff800000);

#pragma unroll
    for (int it = 0; it < 4; it++) {
        int f   = tid + it * 256;       // 0..1023
        int row = f >> 3;
        int ch  = f & 7;
        const __half* sp = Qf + base + (size_t)(qb * 128 + row) * DKK + ch * 8;
        cp16(sQ + row * AP + ch * 16, sp);
    }
    issue_kv(sKV, Kf, Vf, base, 0, tid);
    CP_COMMIT();
    issue_kv(sKV + ASTG_B, Kf, Vf, base, 1, tid);
    CP_COMMIT();

    CP_WAIT1();
    __syncthreads();

    const uint32_t lrow = (lane & 7) + ((lane >> 3) & 1) * 8;
    const uint32_t kb16 = ((lane >> 4) & 1) * 16;
    uint32_t qf[4][4];
#pragma unroll
    for (int ks = 0; ks < 4; ks++) {
        uint32_t a = sQ + (wid * 16 + lrow) * AP + ks * 32 + kb16;
        ldsm4(qf[ks], a);
    }

    float oacc[8][4];
#pragma unroll
    for (int nj = 0; nj < 8; nj++)
#pragma unroll
        for (int q = 0; q < 4; q++) oacc[nj][q] = 0.f;
    float m0 = NINF, m1 = NINF, l0 = 0.f, l1 = 0.f;

    const int r0 = qb * 128 + wid * 16 + g;
    const int r1 = r0 + 8;

    const uint32_t vrow = (lane & 7) + ((lane >> 4) & 1) * 8;
    const uint32_t vb16 = ((lane >> 3) & 1) * 16;

    for (int kb = 0; kb < nkb; kb++) {
        if (kb + 1 < nkb) CP_WAIT1(); else CP_WAIT0();
        __syncthreads();

        const uint32_t sK = sKV + (kb & 1) * ASTG_B;
        const uint32_t sV = sK + KT_B;

        // ---- S = Q*K (fp16 single-term) ----
        float sf[8][4];
#pragma unroll
        for (int nj = 0; nj < 8; nj++)
#pragma unroll
            for (int q = 0; q < 4; q++) sf[nj][q] = 0.f;

#pragma unroll
        for (int ks = 0; ks < 4; ks++) {
#pragma unroll
            for (int ntp = 0; ntp < 2; ntp++) {
                uint32_t kfr[2][4];
#pragma unroll
                for (int nt2 = 0; nt2 < 2; nt2++) {
                    uint32_t ba = sK + ((ntp * 2 + nt2) * 16 + lrow) * AP + ks * 32 + kb16;
                    ldsm4(kfr[nt2], ba);
                }
#pragma unroll
                for (int nt2 = 0; nt2 < 2; nt2++) {
#pragma unroll
                    for (int sel = 0; sel < 2; sel++) {
                        const int nj = (ntp * 2 + nt2) * 2 + sel;
                        mma16816h(sf[nj], qf[ks], kfr[nt2][sel], kfr[nt2][sel + 2]);
                    }
                }
            }
        }

        // ---- causal mask ----
        if (kb >= 2 * qb) {
#pragma unroll
            for (int nj = 0; nj < 8; nj++) {
                int c0 = kb * 64 + nj * 8 + 2 * t;
                if (c0 > r0)     sf[nj][0] = NINF;
                if (c0 + 1 > r0) sf[nj][1] = NINF;
                if (c0 > r1)     sf[nj][2] = NINF;
                if (c0 + 1 > r1) sf[nj][3] = NINF;
            }
        }

        // ---- online softmax (base-2 domain) ----
        float mx0 = sf[0][0], mx1 = sf[0][2];
#pragma unroll
        for (int nj = 0; nj < 8; nj++) {
            mx0 = fmaxf(mx0, fmaxf(sf[nj][0], sf[nj][1]));
            mx1 = fmaxf(mx1, fmaxf(sf[nj][2], sf[nj][3]));
        }
        mx0 = fmaxf(mx0, __shfl_xor_sync(0xffffffffu, mx0, 1));
        mx0 = fmaxf(mx0, __shfl_xor_sync(0xffffffffu, mx0, 2));
        mx1 = fmaxf(mx1, __shfl_xor_sync(0xffffffffu, mx1, 1));
        mx1 = fmaxf(mx1, __shfl_xor_sync(0xffffffffu, mx1, 2));
        float mn0 = fmaxf(m0, mx0), mn1 = fmaxf(m1, mx1);
        float al0 = ex2(m0 - mn0), al1 = ex2(m1 - mn1);
        m0 = mn0; m1 = mn1;

        float s0 = 0.f, s1 = 0.f;
#pragma unroll
        for (int nj = 0; nj < 8; nj++) {
            sf[nj][0] = ex2(sf[nj][0] - m0);
            sf[nj][1] = ex2(sf[nj][1] - m0);
            sf[nj][2] = ex2(sf[nj][2] - m1);
            sf[nj][3] = ex2(sf[nj][3] - m1);
            s0 += sf[nj][0] + sf[nj][1];
            s1 += sf[nj][2] + sf[nj][3];
        }
        s0 += __shfl_xor_sync(0xffffffffu, s0, 1);
        s0 += __shfl_xor_sync(0xffffffffu, s0, 2);
        s1 += __shfl_xor_sync(0xffffffffu, s1, 1);
        s1 += __shfl_xor_sync(0xffffffffu, s1, 2);
        l0 = l0 * al0 + s0;
        l1 = l1 * al1 + s1;

#pragma unroll
        for (int nj = 0; nj < 8; nj++) {
            oacc[nj][0] *= al0; oacc[nj][1] *= al0;
            oacc[nj][2] *= al1; oacc[nj][3] *= al1;
        }

        // ---- O += P * V  (fp16 single-term) ----
#pragma unroll
        for (int ks = 0; ks < 4; ks++) {
            uint32_t pa[4];
            pa[0] = packhf(sf[2 * ks][0],     sf[2 * ks][1]);
            pa[1] = packhf(sf[2 * ks][2],     sf[2 * ks][3]);
            pa[2] = packhf(sf[2 * ks + 1][0], sf[2 * ks + 1][1]);
            pa[3] = packhf(sf[2 * ks + 1][2], sf[2 * ks + 1][3]);
#pragma unroll
            for (int ntp = 0; ntp < 2; ntp++) {
                uint32_t vfr[2][4];
#pragma unroll
                for (int nt2 = 0; nt2 < 2; nt2++) {
                    uint32_t va = sV + (ks * 16 + vrow) * AP + (ntp * 2 + nt2) * 32 + vb16;
                    ldsm4t(vfr[nt2], va);
                }
#pragma unroll
                for (int nt2 = 0; nt2 < 2; nt2++) {
#pragma unroll
                    for (int sel = 0; sel < 2; sel++) {
                        const int nj = (ntp * 2 + nt2) * 2 + sel;
                        mma16816h(oacc[nj], pa, vfr[nt2][sel], vfr[nt2][sel + 2]);
                    }
                }
            }
        }
        __syncthreads();

        if (kb + 2 < nkb) {
            issue_kv(sKV + (kb & 1) * ASTG_B, Kf, Vf, base, kb + 2, tid);
            CP_COMMIT();
        }
    }

    // ---- epilogue: fp16 AO at [b*S+s][h*64+dk] ----
    const float inv0 = 1.0f / l0;
    const float inv1 = 1.0f / l1;
    const int b = bh >> 4, h = bh & 15;
    const size_t row0 = (size_t)(b * SS + r0) * DM;
    const size_t row1 = (size_t)(b * SS + r1) * DM;
#pragma unroll
    for (int nj = 0; nj < 8; nj++) {
        const int e = h * 64 + nj * 8 + 2 * t;
        *(uint32_t*)&AOf[row0 + e] = packhf(oacc[nj][0] * inv0, oacc[nj][1] * inv0);
        *(uint32_t*)&AOf[row1 + e] = packhf(oacc[nj][2] * inv1, oacc[nj][3] * inv1);
    }
}

// ---------------------------------------------------------------------------
extern "C" void kernel_launch(void* const* d_in, const int* in_sizes, int n_in,
                              void* d_out, int out_size)
{
    const float* x  = (const float*)d_in[0];
    const float* Wq = (const float*)d_in[1];
    const float* Wk = (const float*)d_in[2];
    const float* Wv = (const float*)d_in[3];
    const float* Wo = (const float*)d_in[4];
    const int*   tp = (const int*)  d_in[5];
    float* out = (float*)d_out;

    float* gRope;
    __half *xf, *wf, *vf, *aof, *qf, *kf;
    cudaGetSymbolAddress((void**)&gRope, g_rope);
    cudaGetSymbolAddress((void**)&xf,  g_xf);
    cudaGetSymbolAddress((void**)&wf,  g_wf);
    cudaGetSymbolAddress((void**)&vf,  g_vf);
    cudaGetSymbolAddress((void**)&aof, g_aof);
    cudaGetSymbolAddress((void**)&qf,  g_Qf);
    cudaGetSymbolAddress((void**)&kf,  g_Kf);

    cudaFuncSetAttribute(gemm_h,   cudaFuncAttributeMaxDynamicSharedMemorySize, GSMEM);
    cudaFuncSetAttribute(attn_mma, cudaFuncAttributeMaxDynamicSharedMemorySize, ASMEM);

    const int nx4 = MTOT * DM / 4;
    const int nw4 = DM * DM / 4;
    cvt_kernel<<<nx4 / 256, 256>>>(x, xf, nx4);
    dim3 wgrid(nw4 / 256, 4);
    cvt_w_kernel<<<wgrid, 256>>>(Wq, Wk, Wv, Wo, wf);
    rope_init_kernel<<<SS * 32 / 256, 256>>>(tp, gRope);

    dim3 qkvgrid(MTOT / 128, 24);   // (64, 24)
    gemm_h<<<qkvgrid, 256, GSMEM>>>(xf, wf, nullptr, qf, kf, vf, gRope, 0);

    attn_mma<<<1024, 256, ASMEM>>>(qf, kf, vf, aof);

    dim3 wogrid(MTOT / 128, 8);     // (64, 8)
    gemm_h<<<wogrid, 256, GSMEM>>>(aof, wf, out, qf, kf, vf, gRope, 1);
}